// round 1
// baseline (speedup 1.0000x reference)
#include <cuda_runtime.h>

#define NA   9
#define NAA  81
#define HH   192
#define WWID 192
#define HW   (192*192)
#define CIN  32
#define MOUT 4
#define ND   9

typedef unsigned long long u64;

// scratch: mask pre-scaled by 81/sum (folds the mask_avg division)
__device__ float g_mask[NAA * HW];

__device__ __forceinline__ u64 fma2(u64 a, u64 b, u64 c) {
    u64 d; asm("fma.rn.f32x2 %0, %1, %2, %3;" : "=l"(d) : "l"(a), "l"(b), "l"(c)); return d;
}
__device__ __forceinline__ u64 mul2(u64 a, u64 b) {
    u64 d; asm("mul.rn.f32x2 %0, %1, %2;" : "=l"(d) : "l"(a), "l"(b)); return d;
}
__device__ __forceinline__ u64 pack2(float lo, float hi) {
    u64 d; asm("mov.b64 %0, {%1, %2};" : "=l"(d) : "f"(lo), "f"(hi)); return d;
}

__global__ void mask_scale_k(const float* __restrict__ mask) {
    int idx = blockIdx.x * 256 + threadIdx.x;
    if (idx >= HW) return;
    float s = 0.f;
    #pragma unroll 9
    for (int a = 0; a < NAA; a++) s += mask[a * HW + idx];
    float inv = 81.0f / s;
    #pragma unroll 9
    for (int a = 0; a < NAA; a++) g_mask[a * HW + idx] = mask[a * HW + idx] * inv;
}

template <bool CHK>
__device__ __forceinline__ void accumulate(const float* __restrict__ xc,
                                           const u64 (* __restrict__ sW)[4],
                                           int i, int j, u64 acc[9][4]) {
    const int base = i * WWID + j;
    #pragma unroll 1
    for (int p = 0; p < 9; p++) {
        const int pp = 4 - p;
        #pragma unroll 1
        for (int q = 0; q < 9; q++) {
            const int qq = 4 - q;
            const int pq = p * 9 + q;
            u64 mask2 = *(const u64*)(g_mask + pq * HW + base);
            u64 wm0 = mul2(sW[pq][0], mask2);
            u64 wm1 = mul2(sW[pq][1], mask2);
            u64 wm2 = mul2(sW[pq][2], mask2);
            u64 wm3 = mul2(sW[pq][3], mask2);
            const float* xv = xc + pq * HW;
            const int stp = pp * WWID + qq;
            if ((qq & 1) == 0) {
                // d*qq always even -> aligned float2 loads for the pixel pair
                #pragma unroll
                for (int dd = 0; dd < 9; dd++) {
                    const int d = dd - 4;
                    u64 x2;
                    if (CHK) {
                        int r = i + d * pp, col = j + d * qq;
                        bool ok = ((unsigned)r < (unsigned)HH) && ((unsigned)col < (unsigned)(WWID - 1));
                        x2 = ok ? *(const u64*)(xv + base + d * stp) : 0ull;
                    } else {
                        x2 = *(const u64*)(xv + base + d * stp);
                    }
                    acc[dd][0] = fma2(wm0, x2, acc[dd][0]);
                    acc[dd][1] = fma2(wm1, x2, acc[dd][1]);
                    acc[dd][2] = fma2(wm2, x2, acc[dd][2]);
                    acc[dd][3] = fma2(wm3, x2, acc[dd][3]);
                }
            } else {
                #pragma unroll
                for (int dd = 0; dd < 9; dd++) {
                    const int d = dd - 4;
                    u64 x2;
                    if ((d & 1) == 0) {
                        // even shift: aligned float2
                        if (CHK) {
                            int r = i + d * pp, col = j + d * qq;
                            bool ok = ((unsigned)r < (unsigned)HH) && ((unsigned)col < (unsigned)(WWID - 1));
                            x2 = ok ? *(const u64*)(xv + base + d * stp) : 0ull;
                        } else {
                            x2 = *(const u64*)(xv + base + d * stp);
                        }
                    } else {
                        // odd shift: two scalar loads, pack
                        const int off = base + d * stp;
                        float lo, hi;
                        if (CHK) {
                            int r = i + d * pp, col = j + d * qq;
                            bool rok = ((unsigned)r < (unsigned)HH);
                            lo = (rok && (unsigned)col       < (unsigned)WWID) ? xv[off]     : 0.f;
                            hi = (rok && (unsigned)(col + 1) < (unsigned)WWID) ? xv[off + 1] : 0.f;
                        } else {
                            lo = xv[off];
                            hi = xv[off + 1];
                        }
                        x2 = pack2(lo, hi);
                    }
                    acc[dd][0] = fma2(wm0, x2, acc[dd][0]);
                    acc[dd][1] = fma2(wm1, x2, acc[dd][1]);
                    acc[dd][2] = fma2(wm2, x2, acc[dd][2]);
                    acc[dd][3] = fma2(wm3, x2, acc[dd][3]);
                }
            }
        }
    }
}

__global__ __launch_bounds__(256, 2)
void build_cost_k(const float* __restrict__ x,
                  const float* __restrict__ W,
                  float* __restrict__ out) {
    __shared__ u64 sW[NAA][4];  // W[c*4+m][pq], broadcast-packed (v,v)
    const int tx = threadIdx.x;          // 0..15  (pixel pair in j)
    const int ty = threadIdx.y;          // 0..15  (row)
    const int tid = ty * 16 + tx;
    const int c = blockIdx.z;
    const int j0 = blockIdx.x * 32;
    const int i0 = blockIdx.y * 16;

    for (int t = tid; t < NAA * MOUT; t += 256) {
        int m = t & 3, pq = t >> 2;
        float v = W[(c * MOUT + m) * NAA + pq];
        sW[pq][m] = pack2(v, v);
    }
    __syncthreads();

    const int i = i0 + ty;
    const int j = j0 + tx * 2;

    u64 acc[9][4];
    #pragma unroll
    for (int dd = 0; dd < 9; dd++)
        #pragma unroll
        for (int m = 0; m < 4; m++) acc[dd][m] = 0ull;

    const float* xc = x + (size_t)c * NAA * HW;

    const bool interior = (i0 >= 16) && (i0 + 16 <= HH - 16) &&
                          (j0 >= 16) && (j0 + 32 <= WWID - 16);
    if (interior) accumulate<false>(xc, sW, i, j, acc);
    else          accumulate<true>(xc, sW, i, j, acc);

    const int pix = i * WWID + j;
    #pragma unroll
    for (int m = 0; m < 4; m++)
        #pragma unroll
        for (int dd = 0; dd < 9; dd++)
            *(u64*)(out + (size_t)((c * MOUT + m) * ND + dd) * HW + pix) = acc[dd][m];
}

extern "C" void kernel_launch(void* const* d_in, const int* in_sizes, int n_in,
                              void* d_out, int out_size) {
    const float* x    = (const float*)d_in[0];  // [1,32,81,192,192]
    const float* mask = (const float*)d_in[1];  // [1,81,192,192]
    const float* W    = (const float*)d_in[2];  // [128,81]
    float* out = (float*)d_out;                 // [1,128,9,192,192]

    mask_scale_k<<<(HW + 255) / 256, 256>>>(mask);

    dim3 grid(WWID / 32, HH / 16, CIN);  // channel slowest -> L2 reuse of x per channel
    dim3 block(16, 16);
    build_cost_k<<<grid, block>>>(x, W, out);
}

// round 2
// speedup vs baseline: 1.0954x; 1.0954x over previous
#include <cuda_runtime.h>

#define NA   9
#define NAA  81
#define HH   192
#define WWID 192
#define HW   (192*192)
#define CIN  32
#define MOUT 4
#define ND   9

typedef unsigned long long u64;

// scratch: mask pre-scaled by 81/sum (folds the mask_avg division)
__device__ float g_mask[NAA * HW];

__device__ __forceinline__ u64 fma2(u64 a, u64 b, u64 c) {
    u64 d; asm("fma.rn.f32x2 %0, %1, %2, %3;" : "=l"(d) : "l"(a), "l"(b), "l"(c)); return d;
}
__device__ __forceinline__ u64 mul2(u64 a, u64 b) {
    u64 d; asm("mul.rn.f32x2 %0, %1, %2;" : "=l"(d) : "l"(a), "l"(b)); return d;
}
__device__ __forceinline__ u64 pack2(float lo, float hi) {
    u64 d; asm("mov.b64 %0, {%1, %2};" : "=l"(d) : "f"(lo), "f"(hi)); return d;
}

__global__ void mask_scale_k(const float* __restrict__ mask) {
    int idx = blockIdx.x * 256 + threadIdx.x;
    if (idx >= HW) return;
    float s = 0.f;
    #pragma unroll 9
    for (int a = 0; a < NAA; a++) s += mask[a * HW + idx];
    float inv = 81.0f / s;
    #pragma unroll 9
    for (int a = 0; a < NAA; a++) g_mask[a * HW + idx] = mask[a * HW + idx] * inv;
}

template <bool CHK>
__device__ __forceinline__ void accumulate(const float* __restrict__ xc,
                                           const u64 (* __restrict__ sW)[4],
                                           int i, int j, u64 acc[9][4]) {
    const int base = i * WWID + j;
    #pragma unroll 1
    for (int p = 0; p < 9; p++) {
        const int pp = 4 - p;
        const int prow = pp * WWID;
        const float* bp = xc + base + p * 9 * HW;       // view (p,0) at center pixel
        const float* mp = g_mask + base + p * 9 * HW;   // mask (p,0) at center pixel

        // 9 per-d base pointers: all remaining offsets are compile-time immediates
        const float* bpd[9];
        int rowv[9];
        #pragma unroll
        for (int dd = 0; dd < 9; dd++) {
            bpd[dd] = bp + (dd - 4) * prow;
            if (CHK) rowv[dd] = i + (dd - 4) * pp;
        }

        #pragma unroll
        for (int q = 0; q < 9; q++) {
            const int qq = 4 - q;                      // compile-time
            const int pq = p * 9 + q;
            u64 mask2 = *(const u64*)(mp + q * HW);
            u64 wm0 = mul2(sW[pq][0], mask2);
            u64 wm1 = mul2(sW[pq][1], mask2);
            u64 wm2 = mul2(sW[pq][2], mask2);
            u64 wm3 = mul2(sW[pq][3], mask2);

            #pragma unroll
            for (int dd = 0; dd < 9; dd++) {
                const int d = dd - 4;                  // compile-time
                const int off = q * HW + d * qq;       // compile-time immediate
                u64 x2;
                if (((qq & 1) == 0) || ((d & 1) == 0)) {
                    // shift even -> aligned float2 for the pixel pair
                    if (CHK) {
                        int colv = j + d * qq;
                        bool ok = ((unsigned)rowv[dd] < (unsigned)HH) &&
                                  ((unsigned)colv < (unsigned)(WWID - 1));
                        x2 = ok ? *(const u64*)(bpd[dd] + off) : 0ull;
                    } else {
                        x2 = *(const u64*)(bpd[dd] + off);
                    }
                } else {
                    // odd shift: two scalar loads, pack
                    float lo, hi;
                    if (CHK) {
                        int colv = j + d * qq;
                        bool rok = ((unsigned)rowv[dd] < (unsigned)HH);
                        lo = (rok && (unsigned)colv       < (unsigned)WWID) ? bpd[dd][off]     : 0.f;
                        hi = (rok && (unsigned)(colv + 1) < (unsigned)WWID) ? bpd[dd][off + 1] : 0.f;
                    } else {
                        lo = bpd[dd][off];
                        hi = bpd[dd][off + 1];
                    }
                    x2 = pack2(lo, hi);
                }
                acc[dd][0] = fma2(wm0, x2, acc[dd][0]);
                acc[dd][1] = fma2(wm1, x2, acc[dd][1]);
                acc[dd][2] = fma2(wm2, x2, acc[dd][2]);
                acc[dd][3] = fma2(wm3, x2, acc[dd][3]);
            }
        }
    }
}

__global__ __launch_bounds__(256, 2)
void build_cost_k(const float* __restrict__ x,
                  const float* __restrict__ W,
                  float* __restrict__ out) {
    __shared__ u64 sW[NAA][4];  // W[c*4+m][pq], broadcast-packed (v,v)
    const int tx = threadIdx.x;          // 0..15  (pixel pair in j)
    const int ty = threadIdx.y;          // 0..15  (row)
    const int tid = ty * 16 + tx;
    const int c = blockIdx.z;
    const int j0 = blockIdx.x * 32;
    const int i0 = blockIdx.y * 16;

    for (int t = tid; t < NAA * MOUT; t += 256) {
        int m = t & 3, pq = t >> 2;
        float v = W[(c * MOUT + m) * NAA + pq];
        sW[pq][m] = pack2(v, v);
    }
    __syncthreads();

    const int i = i0 + ty;
    const int j = j0 + tx * 2;

    u64 acc[9][4];
    #pragma unroll
    for (int dd = 0; dd < 9; dd++)
        #pragma unroll
        for (int m = 0; m < 4; m++) acc[dd][m] = 0ull;

    const float* xc = x + (size_t)c * NAA * HW;

    const bool interior = (i0 >= 16) && (i0 + 16 <= HH - 16) &&
                          (j0 >= 16) && (j0 + 32 <= WWID - 16);
    if (interior) accumulate<false>(xc, sW, i, j, acc);
    else          accumulate<true>(xc, sW, i, j, acc);

    const int pix = i * WWID + j;
    #pragma unroll
    for (int m = 0; m < 4; m++)
        #pragma unroll
        for (int dd = 0; dd < 9; dd++)
            *(u64*)(out + (size_t)((c * MOUT + m) * ND + dd) * HW + pix) = acc[dd][m];
}

extern "C" void kernel_launch(void* const* d_in, const int* in_sizes, int n_in,
                              void* d_out, int out_size) {
    const float* x    = (const float*)d_in[0];  // [1,32,81,192,192]
    const float* mask = (const float*)d_in[1];  // [1,81,192,192]
    const float* W    = (const float*)d_in[2];  // [128,81]
    float* out = (float*)d_out;                 // [1,128,9,192,192]

    mask_scale_k<<<(HW + 255) / 256, 256>>>(mask);

    dim3 grid(WWID / 32, HH / 16, CIN);  // channel slowest -> L2 reuse of x per channel
    dim3 block(16, 16);
    build_cost_k<<<grid, block>>>(x, W, out);
}

// round 4
// speedup vs baseline: 1.7134x; 1.5642x over previous
#include <cuda_runtime.h>

#define NA   9
#define NAA  81
#define HH   192
#define WWID 192
#define HW   (192*192)
#define CIN  32
#define MOUT 4
#define ND   9

typedef unsigned long long u64;

// scratch: mask pre-scaled by 81/sum (folds the mask_avg division)
__device__ float g_mask[NAA * HW];

__device__ __forceinline__ u64 fma2(u64 a, u64 b, u64 c) {
    u64 d; asm("fma.rn.f32x2 %0, %1, %2, %3;" : "=l"(d) : "l"(a), "l"(b), "l"(c)); return d;
}
__device__ __forceinline__ u64 mul2(u64 a, u64 b) {
    u64 d; asm("mul.rn.f32x2 %0, %1, %2;" : "=l"(d) : "l"(a), "l"(b)); return d;
}
__device__ __forceinline__ u64 pack2(float lo, float hi) {
    u64 d; asm("mov.b64 %0, {%1, %2};" : "=l"(d) : "f"(lo), "f"(hi)); return d;
}

__global__ void mask_scale_k(const float* __restrict__ mask) {
    int idx = blockIdx.x * 256 + threadIdx.x;
    if (idx >= HW) return;
    float s = 0.f;
    #pragma unroll 9
    for (int a = 0; a < NAA; a++) s += mask[a * HW + idx];
    float inv = 81.0f / s;
    #pragma unroll 9
    for (int a = 0; a < NAA; a++) g_mask[a * HW + idx] = mask[a * HW + idx] * inv;
}

// Interior path: p,q,d fully unrolled -> every offset is a compile-time
// immediate off ONE base pointer. No per-load IMAD, minimal live pointers.
__device__ __forceinline__ void accumulate_fast(const float* __restrict__ xc,
                                                const u64 (* __restrict__ sW)[4],
                                                int base, u64 acc[9][4]) {
    const float* b0 = xc + base;               // x view (0,0) at center pixel
    const float* m0 = g_mask + base;           // mask (0,0) at center pixel
    #pragma unroll
    for (int p = 0; p < 9; p++) {
        const int pp = 4 - p;
        #pragma unroll
        for (int q = 0; q < 9; q++) {
            const int qq = 4 - q;
            const int pq = p * 9 + q;
            u64 mask2 = *(const u64*)(m0 + pq * HW);
            u64 wm0 = mul2(sW[pq][0], mask2);
            u64 wm1 = mul2(sW[pq][1], mask2);
            u64 wm2 = mul2(sW[pq][2], mask2);
            u64 wm3 = mul2(sW[pq][3], mask2);
            #pragma unroll
            for (int dd = 0; dd < 9; dd++) {
                const int d = dd - 4;
                const int off = pq * HW + d * (pp * WWID + qq);  // literal
                u64 x2;
                if (((qq & 1) == 0) || ((d & 1) == 0)) {
                    x2 = *(const u64*)(b0 + off);
                } else {
                    x2 = pack2(b0[off], b0[off + 1]);
                }
                acc[dd][0] = fma2(wm0, x2, acc[dd][0]);
                acc[dd][1] = fma2(wm1, x2, acc[dd][1]);
                acc[dd][2] = fma2(wm2, x2, acc[dd][2]);
                acc[dd][3] = fma2(wm3, x2, acc[dd][3]);
            }
        }
    }
}

// Boundary path: rolled p-loop with full bounds checks (45% of CTAs, but
// runs concurrently with interior CTAs; kept rolled to bound code size).
__device__ __forceinline__ void accumulate_chk(const float* __restrict__ xc,
                                               const u64 (* __restrict__ sW)[4],
                                               int i, int j, u64 acc[9][4]) {
    const int base = i * WWID + j;
    #pragma unroll 1
    for (int p = 0; p < 9; p++) {
        const int pp = 4 - p;
        const int prow = pp * WWID;
        const float* bp = xc + base + p * 9 * HW;
        const float* mp = g_mask + base + p * 9 * HW;
        const float* bpd[9];
        int rowv[9];
        #pragma unroll
        for (int dd = 0; dd < 9; dd++) {
            bpd[dd] = bp + (dd - 4) * prow;
            rowv[dd] = i + (dd - 4) * pp;
        }
        #pragma unroll
        for (int q = 0; q < 9; q++) {
            const int qq = 4 - q;
            const int pq = p * 9 + q;
            u64 mask2 = *(const u64*)(mp + q * HW);
            u64 wm0 = mul2(sW[pq][0], mask2);
            u64 wm1 = mul2(sW[pq][1], mask2);
            u64 wm2 = mul2(sW[pq][2], mask2);
            u64 wm3 = mul2(sW[pq][3], mask2);
            #pragma unroll
            for (int dd = 0; dd < 9; dd++) {
                const int d = dd - 4;
                const int off = q * HW + d * qq;
                int colv = j + d * qq;
                bool rok = ((unsigned)rowv[dd] < (unsigned)HH);
                u64 x2;
                if (((qq & 1) == 0) || ((d & 1) == 0)) {
                    bool ok = rok && ((unsigned)colv < (unsigned)(WWID - 1));
                    x2 = ok ? *(const u64*)(bpd[dd] + off) : 0ull;
                } else {
                    float lo = (rok && (unsigned)colv       < (unsigned)WWID) ? bpd[dd][off]     : 0.f;
                    float hi = (rok && (unsigned)(colv + 1) < (unsigned)WWID) ? bpd[dd][off + 1] : 0.f;
                    x2 = pack2(lo, hi);
                }
                acc[dd][0] = fma2(wm0, x2, acc[dd][0]);
                acc[dd][1] = fma2(wm1, x2, acc[dd][1]);
                acc[dd][2] = fma2(wm2, x2, acc[dd][2]);
                acc[dd][3] = fma2(wm3, x2, acc[dd][3]);
            }
        }
    }
}

__global__ __launch_bounds__(256, 2)
void build_cost_k(const float* __restrict__ x,
                  const float* __restrict__ W,
                  float* __restrict__ out) {
    __shared__ u64 sW[NAA][4];  // W[c*4+m][pq], broadcast-packed (v,v)
    const int tx = threadIdx.x;          // 0..15  (pixel pair in j)
    const int ty = threadIdx.y;          // 0..15  (row)
    const int tid = ty * 16 + tx;
    const int c = blockIdx.z;
    const int j0 = blockIdx.x * 32;
    const int i0 = blockIdx.y * 16;

    for (int t = tid; t < NAA * MOUT; t += 256) {
        int m = t & 3, pq = t >> 2;
        float v = W[(c * MOUT + m) * NAA + pq];
        sW[pq][m] = pack2(v, v);
    }
    __syncthreads();

    const int i = i0 + ty;
    const int j = j0 + tx * 2;

    u64 acc[9][4];
    #pragma unroll
    for (int dd = 0; dd < 9; dd++)
        #pragma unroll
        for (int m = 0; m < 4; m++) acc[dd][m] = 0ull;

    const float* xc = x + (size_t)c * NAA * HW;

    const bool interior = (i0 >= 16) && (i0 + 16 <= HH - 16) &&
                          (j0 >= 16) && (j0 + 32 <= WWID - 16);
    if (interior) accumulate_fast(xc, sW, i * WWID + j, acc);
    else          accumulate_chk(xc, sW, i, j, acc);

    const int pix = i * WWID + j;
    #pragma unroll
    for (int m = 0; m < 4; m++)
        #pragma unroll
        for (int dd = 0; dd < 9; dd++)
            *(u64*)(out + (size_t)((c * MOUT + m) * ND + dd) * HW + pix) = acc[dd][m];
}

extern "C" void kernel_launch(void* const* d_in, const int* in_sizes, int n_in,
                              void* d_out, int out_size) {
    const float* x    = (const float*)d_in[0];  // [1,32,81,192,192]
    const float* mask = (const float*)d_in[1];  // [1,81,192,192]
    const float* W    = (const float*)d_in[2];  // [128,81]
    float* out = (float*)d_out;                 // [1,128,9,192,192]

    mask_scale_k<<<(HW + 255) / 256, 256>>>(mask);

    dim3 grid(WWID / 32, HH / 16, CIN);  // channel slowest -> L2 reuse of x per channel
    dim3 block(16, 16);
    build_cost_k<<<grid, block>>>(x, W, out);
}

// round 6
// speedup vs baseline: 2.2974x; 1.3408x over previous
#include <cuda_runtime.h>

#define NA   9
#define NAA  81
#define HH   192
#define WWID 192
#define HW   (192*192)
#define CIN  32
#define MOUT 4
#define ND   9

typedef unsigned long long u64;

// scratch: mask pre-scaled by 81/sum (folds the mask_avg division)
__device__ float g_mask[NAA * HW];

__device__ __forceinline__ u64 fma2(u64 a, u64 b, u64 c) {
    u64 d; asm("fma.rn.f32x2 %0, %1, %2, %3;" : "=l"(d) : "l"(a), "l"(b), "l"(c)); return d;
}
__device__ __forceinline__ u64 mul2(u64 a, u64 b) {
    u64 d; asm("mul.rn.f32x2 %0, %1, %2;" : "=l"(d) : "l"(a), "l"(b)); return d;
}
__device__ __forceinline__ u64 pack2(float lo, float hi) {
    u64 d; asm("mov.b64 %0, {%1, %2};" : "=l"(d) : "f"(lo), "f"(hi)); return d;
}

__global__ void mask_scale_k(const float* __restrict__ mask) {
    int idx = blockIdx.x * 256 + threadIdx.x;
    if (idx >= HW) return;
    float s = 0.f;
    #pragma unroll 9
    for (int a = 0; a < NAA; a++) s += mask[a * HW + idx];
    float inv = 81.0f / s;
    #pragma unroll 9
    for (int a = 0; a < NAA; a++) g_mask[a * HW + idx] = mask[a * HW + idx] * inv;
}

// Fast (interior) path for one d-group G: handles dd = 3G..3G+2.
// p,q,k fully unrolled; all offsets compile-time.
template <int G>
__device__ __forceinline__ void accumulate_fast(const float* __restrict__ xc,
                                                const u64 (* __restrict__ sW)[4],
                                                int base, u64 acc[3][4]) {
    const float* b0 = xc + base;
    const float* m0 = g_mask + base;
    #pragma unroll
    for (int p = 0; p < 9; p++) {
        const int pp = 4 - p;
        #pragma unroll
        for (int q = 0; q < 9; q++) {
            const int qq = 4 - q;
            const int pq = p * 9 + q;
            u64 mask2 = *(const u64*)(m0 + pq * HW);
            u64 wm0 = mul2(sW[pq][0], mask2);
            u64 wm1 = mul2(sW[pq][1], mask2);
            u64 wm2 = mul2(sW[pq][2], mask2);
            u64 wm3 = mul2(sW[pq][3], mask2);
            #pragma unroll
            for (int k = 0; k < 3; k++) {
                const int d = 3 * G + k - 4;                       // compile-time
                const int off = pq * HW + d * (pp * WWID + qq);    // literal
                u64 x2;
                if (((qq & 1) == 0) || ((d & 1) == 0)) {
                    x2 = *(const u64*)(b0 + off);
                } else {
                    x2 = pack2(b0[off], b0[off + 1]);
                }
                acc[k][0] = fma2(wm0, x2, acc[k][0]);
                acc[k][1] = fma2(wm1, x2, acc[k][1]);
                acc[k][2] = fma2(wm2, x2, acc[k][2]);
                acc[k][3] = fma2(wm3, x2, acc[k][3]);
            }
        }
    }
}

// Boundary path for d-group G: rolled p-loop with full bounds checks.
template <int G>
__device__ __forceinline__ void accumulate_chk(const float* __restrict__ xc,
                                               const u64 (* __restrict__ sW)[4],
                                               int i, int j, u64 acc[3][4]) {
    const int base = i * WWID + j;
    #pragma unroll 1
    for (int p = 0; p < 9; p++) {
        const int pp = 4 - p;
        const int prow = pp * WWID;
        const float* bp = xc + base + p * 9 * HW;
        const float* mp = g_mask + base + p * 9 * HW;
        const float* bpd[3];
        int rowv[3];
        #pragma unroll
        for (int k = 0; k < 3; k++) {
            const int d = 3 * G + k - 4;
            bpd[k] = bp + d * prow;
            rowv[k] = i + d * pp;
        }
        #pragma unroll
        for (int q = 0; q < 9; q++) {
            const int qq = 4 - q;
            const int pq = p * 9 + q;
            u64 mask2 = *(const u64*)(mp + q * HW);
            u64 wm0 = mul2(sW[pq][0], mask2);
            u64 wm1 = mul2(sW[pq][1], mask2);
            u64 wm2 = mul2(sW[pq][2], mask2);
            u64 wm3 = mul2(sW[pq][3], mask2);
            #pragma unroll
            for (int k = 0; k < 3; k++) {
                const int d = 3 * G + k - 4;
                const int off = q * HW + d * qq;
                int colv = j + d * qq;
                bool rok = ((unsigned)rowv[k] < (unsigned)HH);
                u64 x2;
                if (((qq & 1) == 0) || ((d & 1) == 0)) {
                    bool ok = rok && ((unsigned)colv < (unsigned)(WWID - 1));
                    x2 = ok ? *(const u64*)(bpd[k] + off) : 0ull;
                } else {
                    float lo = (rok && (unsigned)colv       < (unsigned)WWID) ? bpd[k][off]     : 0.f;
                    float hi = (rok && (unsigned)(colv + 1) < (unsigned)WWID) ? bpd[k][off + 1] : 0.f;
                    x2 = pack2(lo, hi);
                }
                acc[k][0] = fma2(wm0, x2, acc[k][0]);
                acc[k][1] = fma2(wm1, x2, acc[k][1]);
                acc[k][2] = fma2(wm2, x2, acc[k][2]);
                acc[k][3] = fma2(wm3, x2, acc[k][3]);
            }
        }
    }
}

__global__ __launch_bounds__(256, 4)
void build_cost_k(const float* __restrict__ x,
                  const float* __restrict__ W,
                  float* __restrict__ out) {
    __shared__ u64 sW[NAA][4];  // W[c*4+m][pq], broadcast-packed (v,v)
    const int tx = threadIdx.x;          // 0..15  (pixel pair in j)
    const int ty = threadIdx.y;          // 0..15  (row)
    const int tid = ty * 16 + tx;
    const int c = blockIdx.z / 3;        // z = c*3 + g: d-groups of a channel co-resident
    const int g = blockIdx.z % 3;
    const int j0 = blockIdx.x * 32;
    const int i0 = blockIdx.y * 16;

    for (int t = tid; t < NAA * MOUT; t += 256) {
        int m = t & 3, pq = t >> 2;
        float v = W[(c * MOUT + m) * NAA + pq];
        sW[pq][m] = pack2(v, v);
    }
    __syncthreads();

    const int i = i0 + ty;
    const int j = j0 + tx * 2;

    u64 acc[3][4];
    #pragma unroll
    for (int k = 0; k < 3; k++)
        #pragma unroll
        for (int m = 0; m < 4; m++) acc[k][m] = 0ull;

    const float* xc = x + (size_t)c * NAA * HW;

    const bool interior = (i0 >= 16) && (i0 + 16 <= HH - 16) &&
                          (j0 >= 16) && (j0 + 32 <= WWID - 16);
    const int base = i * WWID + j;
    if (interior) {
        if (g == 0)      accumulate_fast<0>(xc, sW, base, acc);
        else if (g == 1) accumulate_fast<1>(xc, sW, base, acc);
        else             accumulate_fast<2>(xc, sW, base, acc);
    } else {
        if (g == 0)      accumulate_chk<0>(xc, sW, i, j, acc);
        else if (g == 1) accumulate_chk<1>(xc, sW, i, j, acc);
        else             accumulate_chk<2>(xc, sW, i, j, acc);
    }

    #pragma unroll
    for (int m = 0; m < 4; m++)
        #pragma unroll
        for (int k = 0; k < 3; k++) {
            int dd = 3 * g + k;
            *(u64*)(out + (size_t)((c * MOUT + m) * ND + dd) * HW + base) = acc[k][m];
        }
}

extern "C" void kernel_launch(void* const* d_in, const int* in_sizes, int n_in,
                              void* d_out, int out_size) {
    const float* x    = (const float*)d_in[0];  // [1,32,81,192,192]
    const float* mask = (const float*)d_in[1];  // [1,81,192,192]
    const float* W    = (const float*)d_in[2];  // [128,81]
    float* out = (float*)d_out;                 // [1,128,9,192,192]

    mask_scale_k<<<(HW + 255) / 256, 256>>>(mask);

    dim3 grid(WWID / 32, HH / 16, CIN * 3);  // z = c*3 + g
    dim3 block(16, 16);
    build_cost_k<<<grid, block>>>(x, W, out);
}

// round 7
// speedup vs baseline: 2.3513x; 1.0235x over previous
#include <cuda_runtime.h>

#define NA   9
#define NAA  81
#define HH   192
#define WWID 192
#define HW   (192*192)
#define CIN  32
#define MOUT 4
#define ND   9

typedef unsigned long long u64;

// scratch: mask pre-scaled by 81/sum (folds the mask_avg division)
__device__ float g_mask[NAA * HW];

__device__ __forceinline__ u64 fma2(u64 a, u64 b, u64 c) {
    u64 d; asm("fma.rn.f32x2 %0, %1, %2, %3;" : "=l"(d) : "l"(a), "l"(b), "l"(c)); return d;
}
__device__ __forceinline__ u64 mul2(u64 a, u64 b) {
    u64 d; asm("mul.rn.f32x2 %0, %1, %2;" : "=l"(d) : "l"(a), "l"(b)); return d;
}
__device__ __forceinline__ u64 pack2(float lo, float hi) {
    u64 d; asm("mov.b64 %0, {%1, %2};" : "=l"(d) : "f"(lo), "f"(hi)); return d;
}

__global__ void mask_scale_k(const float* __restrict__ mask) {
    int idx = blockIdx.x * 256 + threadIdx.x;
    if (idx >= HW) return;
    float s = 0.f;
    #pragma unroll 9
    for (int a = 0; a < NAA; a++) s += mask[a * HW + idx];
    float inv = 81.0f / s;
    #pragma unroll 9
    for (int a = 0; a < NAA; a++) g_mask[a * HW + idx] = mask[a * HW + idx] * inv;
}

// Fast (interior) path for one d-group G: handles dd = 3G..3G+2.
// p,q,k fully unrolled; all offsets compile-time.
// W read as 2x LDS.128 (dup-packed); t2 = mask*x then 4 fma per d.
template <int G>
__device__ __forceinline__ void accumulate_fast(const float* __restrict__ xc,
                                                const ulonglong2* __restrict__ sWd,
                                                int base, u64 acc[3][4]) {
    const float* b0 = xc + base;
    const float* m0 = g_mask + base;
    #pragma unroll
    for (int p = 0; p < 9; p++) {
        const int pp = 4 - p;
        #pragma unroll
        for (int q = 0; q < 9; q++) {
            const int qq = 4 - q;
            const int pq = p * 9 + q;
            ulonglong2 wA = sWd[pq * 2 + 0];   // (w0,w0),(w1,w1)  LDS.128 broadcast
            ulonglong2 wB = sWd[pq * 2 + 1];   // (w2,w2),(w3,w3)
            u64 mask2 = *(const u64*)(m0 + pq * HW);
            #pragma unroll
            for (int k = 0; k < 3; k++) {
                const int d = 3 * G + k - 4;                       // compile-time
                const int off = pq * HW + d * (pp * WWID + qq);    // literal
                u64 x2;
                if (((qq & 1) == 0) || ((d & 1) == 0)) {
                    x2 = *(const u64*)(b0 + off);
                } else {
                    x2 = pack2(b0[off], b0[off + 1]);
                }
                u64 t2 = mul2(mask2, x2);
                acc[k][0] = fma2(wA.x, t2, acc[k][0]);
                acc[k][1] = fma2(wA.y, t2, acc[k][1]);
                acc[k][2] = fma2(wB.x, t2, acc[k][2]);
                acc[k][3] = fma2(wB.y, t2, acc[k][3]);
            }
        }
    }
}

// Boundary path for d-group G: rolled p-loop with full bounds checks.
template <int G>
__device__ __forceinline__ void accumulate_chk(const float* __restrict__ xc,
                                               const ulonglong2* __restrict__ sWd,
                                               int i, int j, u64 acc[3][4]) {
    const int base = i * WWID + j;
    #pragma unroll 1
    for (int p = 0; p < 9; p++) {
        const int pp = 4 - p;
        const int prow = pp * WWID;
        const float* bp = xc + base + p * 9 * HW;
        const float* mp = g_mask + base + p * 9 * HW;
        const float* bpd[3];
        int rowv[3];
        #pragma unroll
        for (int k = 0; k < 3; k++) {
            const int d = 3 * G + k - 4;
            bpd[k] = bp + d * prow;
            rowv[k] = i + d * pp;
        }
        #pragma unroll
        for (int q = 0; q < 9; q++) {
            const int qq = 4 - q;
            const int pq = p * 9 + q;
            ulonglong2 wA = sWd[pq * 2 + 0];
            ulonglong2 wB = sWd[pq * 2 + 1];
            u64 mask2 = *(const u64*)(mp + q * HW);
            #pragma unroll
            for (int k = 0; k < 3; k++) {
                const int d = 3 * G + k - 4;
                const int off = q * HW + d * qq;
                int colv = j + d * qq;
                bool rok = ((unsigned)rowv[k] < (unsigned)HH);
                u64 x2;
                if (((qq & 1) == 0) || ((d & 1) == 0)) {
                    bool ok = rok && ((unsigned)colv < (unsigned)(WWID - 1));
                    x2 = ok ? *(const u64*)(bpd[k] + off) : 0ull;
                } else {
                    float lo = (rok && (unsigned)colv       < (unsigned)WWID) ? bpd[k][off]     : 0.f;
                    float hi = (rok && (unsigned)(colv + 1) < (unsigned)WWID) ? bpd[k][off + 1] : 0.f;
                    x2 = pack2(lo, hi);
                }
                u64 t2 = mul2(mask2, x2);
                acc[k][0] = fma2(wA.x, t2, acc[k][0]);
                acc[k][1] = fma2(wA.y, t2, acc[k][1]);
                acc[k][2] = fma2(wB.x, t2, acc[k][2]);
                acc[k][3] = fma2(wB.y, t2, acc[k][3]);
            }
        }
    }
}

__global__ __launch_bounds__(256, 4)
void build_cost_k(const float* __restrict__ x,
                  const float* __restrict__ W,
                  float* __restrict__ out) {
    // W dup-packed: sWd[pq*2+0] = {(w0,w0),(w1,w1)}, sWd[pq*2+1] = {(w2,w2),(w3,w3)}
    __shared__ __align__(16) ulonglong2 sWd[NAA * 2];
    const int tx = threadIdx.x;          // 0..15  (pixel pair in j)
    const int ty = threadIdx.y;          // 0..15  (row)
    const int tid = ty * 16 + tx;
    const int c = blockIdx.z / 3;        // z = c*3 + g: d-groups of a channel co-resident
    const int g = blockIdx.z % 3;
    const int j0 = blockIdx.x * 32;
    const int i0 = blockIdx.y * 16;

    for (int t = tid; t < NAA * MOUT; t += 256) {
        int m = t & 3, pq = t >> 2;
        float v = W[(c * MOUT + m) * NAA + pq];
        ((u64*)sWd)[pq * 4 + m] = pack2(v, v);
    }
    __syncthreads();

    const int i = i0 + ty;
    const int j = j0 + tx * 2;

    u64 acc[3][4];
    #pragma unroll
    for (int k = 0; k < 3; k++)
        #pragma unroll
        for (int m = 0; m < 4; m++) acc[k][m] = 0ull;

    const float* xc = x + (size_t)c * NAA * HW;

    const bool interior = (i0 >= 16) && (i0 + 16 <= HH - 16) &&
                          (j0 >= 16) && (j0 + 32 <= WWID - 16);
    const int base = i * WWID + j;
    if (interior) {
        if (g == 0)      accumulate_fast<0>(xc, sWd, base, acc);
        else if (g == 1) accumulate_fast<1>(xc, sWd, base, acc);
        else             accumulate_fast<2>(xc, sWd, base, acc);
    } else {
        if (g == 0)      accumulate_chk<0>(xc, sWd, i, j, acc);
        else if (g == 1) accumulate_chk<1>(xc, sWd, i, j, acc);
        else             accumulate_chk<2>(xc, sWd, i, j, acc);
    }

    #pragma unroll
    for (int m = 0; m < 4; m++)
        #pragma unroll
        for (int k = 0; k < 3; k++) {
            int dd = 3 * g + k;
            *(u64*)(out + (size_t)((c * MOUT + m) * ND + dd) * HW + base) = acc[k][m];
        }
}

extern "C" void kernel_launch(void* const* d_in, const int* in_sizes, int n_in,
                              void* d_out, int out_size) {
    const float* x    = (const float*)d_in[0];  // [1,32,81,192,192]
    const float* mask = (const float*)d_in[1];  // [1,81,192,192]
    const float* W    = (const float*)d_in[2];  // [128,81]
    float* out = (float*)d_out;                 // [1,128,9,192,192]

    mask_scale_k<<<(HW + 255) / 256, 256>>>(mask);

    dim3 grid(WWID / 32, HH / 16, CIN * 3);  // z = c*3 + g
    dim3 block(16, 16);
    build_cost_k<<<grid, block>>>(x, W, out);
}